// round 5
// baseline (speedup 1.0000x reference)
#include <cuda_runtime.h>

// NoTradeRegionRNN: D=2 channel RNN scan, T timesteps, B independent lanes.
// x, returns: (D, T, B) row-major. output: (D, T, B) then hT (D, 1, B).
//
// R5: two adjacent batch lanes per thread, executed with packed f32x2
// (Blackwell FFMA2) so the pair costs one issue slot per op. Clamp/relu run
// as scalar FMNMX on the register halves. Lower bounds are computed in
// NEGATED form (nlb = clamp(fma(a,-slope,-C), -HI, -LO)) because lb is only
// ever used as -lb (g1) and ub-lb (g2) -> fma2/add2, no subtract needed.
// 256 CTAs x 32 threads covers all 148 SMs. PF=8 step software prefetch,
// all in-group offsets compile-time immediates, float2 (LDG.64) traffic.

typedef unsigned long long ull;

__device__ __forceinline__ ull fma2_(ull a, ull b, ull c) {
    ull d; asm("fma.rn.f32x2 %0, %1, %2, %3;" : "=l"(d) : "l"(a), "l"(b), "l"(c)); return d;
}
__device__ __forceinline__ ull mul2_(ull a, ull b) {
    ull d; asm("mul.rn.f32x2 %0, %1, %2;" : "=l"(d) : "l"(a), "l"(b)); return d;
}
__device__ __forceinline__ ull add2_(ull a, ull b) {
    ull d; asm("add.rn.f32x2 %0, %1, %2;" : "=l"(d) : "l"(a), "l"(b)); return d;
}
union F2 { ull u; float2 f; };
__device__ __forceinline__ ull pack2_(float lo, float hi) {
    F2 t; t.f.x = lo; t.f.y = hi; return t.u;
}
__device__ __forceinline__ ull bcast2_(float v) { return pack2_(v, v); }
__device__ __forceinline__ float frcp_(float v) {
    float r; asm("rcp.approx.f32 %0, %1;" : "=f"(r) : "f"(v)); return r;
}
__device__ __forceinline__ ull rcp2_(ull v) {
    F2 t; t.u = v; t.f.x = frcp_(t.f.x); t.f.y = frcp_(t.f.y); return t.u;
}
__device__ __forceinline__ ull clamp2_(ull v, float lo, float hi) {
    F2 t; t.u = v;
    t.f.x = fminf(fmaxf(t.f.x, lo), hi);
    t.f.y = fminf(fmaxf(t.f.y, lo), hi);
    return t.u;
}
__device__ __forceinline__ ull relu2_(ull v) {
    F2 t; t.u = v;
    t.f.x = fmaxf(t.f.x, 0.0f);
    t.f.y = fmaxf(t.f.y, 0.0f);
    return t.u;
}

// ---------------- scalar parameter derivation ----------------
struct ScalarParams {
    float ac, bd;
    float Wi0, Wi1, Wh0, Wh1, W10, W11, W20, W21;
    float C_lbx, LO_lbx, HI_lbx;   // val = clamp(fma(a, slope, C), LO, HI)
    float C_ubx, LO_ubx, HI_ubx;
    float C_lby, LO_lby, HI_lby;
    float C_uby, LO_uby, HI_uby;
};

__device__ __forceinline__ ScalarParams make_params(
    const float* __restrict__ tgt, const float* __restrict__ wi,
    const float* __restrict__ wh,  const float* __restrict__ bh,
    const float* __restrict__ w1,  const float* __restrict__ w2,
    const float* __restrict__ wr)
{
    ScalarParams P;
    const float wr00 = wr[0], wr01 = wr[1], wr10 = wr[2], wr11 = wr[3];
    const float bh0 = bh[0], bh1 = bh[1];
    const float t0 = tgt[0], t1 = tgt[1];
    P.Wi0 = wi[0]; P.Wi1 = wi[1];
    P.Wh0 = wh[0]; P.Wh1 = wh[1];
    P.W10 = w1[0]; P.W11 = w1[1];
    P.W20 = w2[0]; P.W21 = w2[1];
    P.ac = wr10 / wr00;
    P.bd = wr01 / wr11;

    // Corners: k0:(-,-) k1:(-,+) k2:(+,+) k3:(+,-) applied to (bh0, bh1)
    float Cx[4], Cy[4];
    const float s0[4] = {-1.f, -1.f, 1.f, 1.f};
    const float s1[4] = {-1.f,  1.f, 1.f, -1.f};
#pragma unroll
    for (int k = 0; k < 4; ++k) {
        float vx = s0[k] * bh0, vy = s1[k] * bh1;
        Cx[k] = wr00 * vx + wr01 * vy + t0;
        Cy[k] = wr10 * vx + wr11 * vy + t1;
    }
    const bool bdp = (P.bd >= 0.0f);
    const bool acp = (P.ac >= 0.0f);
    // bound: w=(a-c)*slope; val = o - relu(A - relu(w)) == clamp(w+o-A, o-A, o)
    {
        float c = bdp ? Cy[0] : Cy[1], A = fabsf(Cx[1] - Cx[0]), o = bdp ? Cx[1] : Cx[0];
        P.C_lbx = -c * P.bd + o - A; P.LO_lbx = o - A; P.HI_lbx = o;
    }
    {
        float c = bdp ? Cy[3] : Cy[2], A = fabsf(Cx[2] - Cx[3]), o = bdp ? Cx[2] : Cx[3];
        P.C_ubx = -c * P.bd + o - A; P.LO_ubx = o - A; P.HI_ubx = o;
    }
    {
        float c = acp ? Cx[0] : Cx[3], A = fabsf(Cy[0] - Cy[3]), o = acp ? Cy[3] : Cy[0];
        P.C_lby = -c * P.ac + o - A; P.LO_lby = o - A; P.HI_lby = o;
    }
    {
        float c = acp ? Cx[1] : Cx[2], A = fabsf(Cy[1] - Cy[2]), o = acp ? Cy[2] : Cy[1];
        P.C_uby = -c * P.ac + o - A; P.LO_uby = o - A; P.HI_uby = o;
    }
    return P;
}

// ---------------- packed parameter block ----------------
struct PackedParams {
    ull ONE2;
    ull bd2, nbd2, ac2, nac2;
    ull Wi02, Wi12, Wh02, Wh12, W102, W112, W202, W212;
    ull CNlbx2, Cubx2, CNlby2, Cuby2;
    float nlbx_lo, nlbx_hi, ubx_lo, ubx_hi;
    float nlby_lo, nlby_hi, uby_lo, uby_hi;
};

__device__ __forceinline__ PackedParams pack_params(const ScalarParams& P)
{
    PackedParams Q;
    Q.ONE2 = bcast2_(1.0f);
    Q.bd2 = bcast2_(P.bd);  Q.nbd2 = bcast2_(-P.bd);
    Q.ac2 = bcast2_(P.ac);  Q.nac2 = bcast2_(-P.ac);
    Q.Wi02 = bcast2_(P.Wi0); Q.Wi12 = bcast2_(P.Wi1);
    Q.Wh02 = bcast2_(P.Wh0); Q.Wh12 = bcast2_(P.Wh1);
    Q.W102 = bcast2_(P.W10); Q.W112 = bcast2_(P.W11);
    Q.W202 = bcast2_(P.W20); Q.W212 = bcast2_(P.W21);
    // negated lower bounds: nlb = clamp(fma(a, -slope, -C), -HI, -LO)
    Q.CNlbx2 = bcast2_(-P.C_lbx);
    Q.nlbx_lo = -P.HI_lbx; Q.nlbx_hi = -P.LO_lbx;
    Q.Cubx2 = bcast2_(P.C_ubx);
    Q.ubx_lo = P.LO_ubx;   Q.ubx_hi = P.HI_ubx;
    Q.CNlby2 = bcast2_(-P.C_lby);
    Q.nlby_lo = -P.HI_lby; Q.nlby_hi = -P.LO_lby;
    Q.Cuby2 = bcast2_(P.C_uby);
    Q.uby_lo = P.LO_uby;   Q.uby_hi = P.HI_uby;
    return Q;
}

// one packed recurrence step for a lane pair
__device__ __forceinline__ void ntr_step2(const PackedParams& Q,
                                          ull& hx2, ull& hy2,
                                          ull rx2, ull ry2,
                                          ull xx2, ull xy2)
{
    // denom = 1 + hx*rx + hy*ry ; adj = h*(1+r)/denom
    ull d2 = fma2_(hy2, ry2, Q.ONE2);
    d2 = fma2_(hx2, rx2, d2);
    ull inv2 = rcp2_(d2);
    ull nx2 = fma2_(hx2, rx2, hx2);        // hx*(1+rx)
    ull ny2 = fma2_(hy2, ry2, hy2);
    ull ax2 = mul2_(nx2, inv2);
    ull ay2 = mul2_(ny2, inv2);

    // bounds (lower bounds computed negated)
    ull nlbx2 = clamp2_(fma2_(ay2, Q.nbd2, Q.CNlbx2), Q.nlbx_lo, Q.nlbx_hi);
    ull ubx2  = clamp2_(fma2_(ay2, Q.bd2,  Q.Cubx2),  Q.ubx_lo,  Q.ubx_hi);
    ull nlby2 = clamp2_(fma2_(ax2, Q.nac2, Q.CNlby2), Q.nlby_lo, Q.nlby_hi);
    ull uby2  = clamp2_(fma2_(ax2, Q.ac2,  Q.Cuby2),  Q.uby_lo,  Q.uby_hi);

    // g1 = relu(Wi*x + Wh*a - lb) ; g2 = relu(W1*g1 + (ub - lb)) ; h = W2*g2 + ub
    ull g1x2 = relu2_(fma2_(Q.Wi02, xx2, fma2_(Q.Wh02, ax2, nlbx2)));
    ull g1y2 = relu2_(fma2_(Q.Wi12, xy2, fma2_(Q.Wh12, ay2, nlby2)));
    ull dx2 = add2_(ubx2, nlbx2);
    ull dy2 = add2_(uby2, nlby2);
    ull g2x2 = relu2_(fma2_(Q.W102, g1x2, dx2));
    ull g2y2 = relu2_(fma2_(Q.W112, g1y2, dy2));
    hx2 = fma2_(Q.W202, g2x2, ubx2);
    hy2 = fma2_(Q.W212, g2y2, uby2);
}

// ---------------- specialized packed kernel: compile-time T, B ----------------
template <int T, int B, int PF>
__global__ void __launch_bounds__(32)
ntr_rnn_f32x2(const float* __restrict__ x,
              const float* __restrict__ ret,
              const float* __restrict__ tgt,
              const float* __restrict__ wi,
              const float* __restrict__ wh,
              const float* __restrict__ bh,
              const float* __restrict__ w1,
              const float* __restrict__ w2,
              const float* __restrict__ wr,
              float* __restrict__ out,
              int write_hT)
{
    const int tid = blockIdx.x * blockDim.x + threadIdx.x;   // lane-pair id
    const ScalarParams SP = make_params(tgt, wi, wh, bh, w1, w2, wr);
    const PackedParams Q = pack_params(SP);

    constexpr int STEPS = T - 1;
    constexpr int MAIN_END = ((STEPS - PF) / PF) * PF;
    constexpr int REM_AFTER_A = STEPS - MAIN_END - PF;
    constexpr int B2 = B / 2;                    // lane pairs per timestep
    constexpr size_t TB2 = (size_t)T * (size_t)B2;

    const ull* r0 = (const ull*)ret + tid;
    const ull* r1 = (const ull*)ret + TB2 + tid;
    const ull* x0 = (const ull*)x + tid + B2;    // t = 1
    const ull* x1 = (const ull*)x + TB2 + tid + B2;
    ull* o0 = (ull*)out + tid + B2;              // t = 1
    ull* o1 = (ull*)out + TB2 + tid + B2;

    // h0 = x[:, 0, :]
    ull hx2 = __ldg((const ull*)x + tid);
    ull hy2 = __ldg((const ull*)x + TB2 + tid);
    ((ull*)out)[tid] = hx2;
    ((ull*)out)[TB2 + tid] = hy2;

    // prologue: prefetch buffers for steps 0..PF-1
    ull fr0[PF], fr1[PF], fx0[PF], fx1[PF];
#pragma unroll
    for (int j = 0; j < PF; ++j) {
        fr0[j] = __ldcs(r0 + (size_t)j * B2);
        fr1[j] = __ldcs(r1 + (size_t)j * B2);
        fx0[j] = __ldcs(x0 + (size_t)j * B2);
        fx1[j] = __ldcs(x1 + (size_t)j * B2);
    }

    // main loop: full groups with unconditional prefetch
    for (int s = 0; s < MAIN_END; s += PF) {
#pragma unroll
        for (int j = 0; j < PF; ++j) {
            ull rx = fr0[j], ry = fr1[j], xx = fx0[j], xy = fx1[j];
            fr0[j] = __ldcs(r0 + (size_t)(j + PF) * B2);
            fr1[j] = __ldcs(r1 + (size_t)(j + PF) * B2);
            fx0[j] = __ldcs(x0 + (size_t)(j + PF) * B2);
            fx1[j] = __ldcs(x1 + (size_t)(j + PF) * B2);
            ntr_step2(Q, hx2, hy2, rx, ry, xx, xy);
            __stcs(o0 + (size_t)j * B2, hx2);
            __stcs(o1 + (size_t)j * B2, hy2);
        }
        r0 += (size_t)PF * B2; r1 += (size_t)PF * B2;
        x0 += (size_t)PF * B2; x1 += (size_t)PF * B2;
        o0 += (size_t)PF * B2; o1 += (size_t)PF * B2;
    }

    // tail group A: compile-time-guarded prefetch
#pragma unroll
    for (int j = 0; j < PF; ++j) {
        ull rx = fr0[j], ry = fr1[j], xx = fx0[j], xy = fx1[j];
        if (j < REM_AFTER_A) {
            fr0[j] = __ldcs(r0 + (size_t)(j + PF) * B2);
            fr1[j] = __ldcs(r1 + (size_t)(j + PF) * B2);
            fx0[j] = __ldcs(x0 + (size_t)(j + PF) * B2);
            fx1[j] = __ldcs(x1 + (size_t)(j + PF) * B2);
        }
        ntr_step2(Q, hx2, hy2, rx, ry, xx, xy);
        __stcs(o0 + (size_t)j * B2, hx2);
        __stcs(o1 + (size_t)j * B2, hy2);
    }
    o0 += (size_t)PF * B2; o1 += (size_t)PF * B2;

    // tail group B: final steps, no prefetch
#pragma unroll
    for (int j = 0; j < PF; ++j) {
        if (j < REM_AFTER_A) {
            ntr_step2(Q, hx2, hy2, fr0[j], fr1[j], fx0[j], fx1[j]);
            __stcs(o0 + (size_t)j * B2, hx2);
            __stcs(o1 + (size_t)j * B2, hy2);
        }
    }

    if (write_hT) {
        ((ull*)out)[2 * TB2 + tid] = hx2;
        ((ull*)out)[2 * TB2 + B2 + tid] = hy2;
    }
}

// ---------------- generic scalar fallback (any T, B) ----------------
__device__ __forceinline__ float relu_(float v) { return fmaxf(v, 0.0f); }
__device__ __forceinline__ float clamp_(float v, float lo, float hi) {
    return fminf(fmaxf(v, lo), hi);
}

__global__ void __launch_bounds__(128)
ntr_rnn_generic(const float* __restrict__ x,
                const float* __restrict__ ret,
                const float* __restrict__ tgt,
                const float* __restrict__ wi,
                const float* __restrict__ wh,
                const float* __restrict__ bh,
                const float* __restrict__ w1,
                const float* __restrict__ w2,
                const float* __restrict__ wr,
                float* __restrict__ out,
                int T, int B, int write_hT)
{
    const int b = blockIdx.x * blockDim.x + threadIdx.x;
    if (b >= B) return;
    const ScalarParams P = make_params(tgt, wi, wh, bh, w1, w2, wr);

    const size_t TB = (size_t)T * (size_t)B;
    const float* r0 = ret + b;
    const float* r1 = ret + TB + b;
    const float* x0 = x + b;
    const float* x1 = x + TB + b;
    float* o0 = out + b;
    float* o1 = out + TB + b;

    float hx = __ldg(x0);
    float hy = __ldg(x1);
    o0[0] = hx; o1[0] = hy;

    for (int t = 1; t < T; ++t) {
        size_t offp = (size_t)(t - 1) * B;
        size_t offt = (size_t)t * B;
        float rx = __ldcs(r0 + offp), ry = __ldcs(r1 + offp);
        float xx = __ldcs(x0 + offt), xy = __ldcs(x1 + offt);

        float denom = fmaf(hx, rx, fmaf(hy, ry, 1.0f));
        float inv = frcp_(denom);
        float ax = fmaf(hx, rx, hx) * inv;
        float ay = fmaf(hy, ry, hy) * inv;
        float lbx = clamp_(fmaf(ay, P.bd, P.C_lbx), P.LO_lbx, P.HI_lbx);
        float ubx = clamp_(fmaf(ay, P.bd, P.C_ubx), P.LO_ubx, P.HI_ubx);
        float lby = clamp_(fmaf(ax, P.ac, P.C_lby), P.LO_lby, P.HI_lby);
        float uby = clamp_(fmaf(ax, P.ac, P.C_uby), P.LO_uby, P.HI_uby);
        float g1x = relu_(fmaf(P.Wi0, xx, fmaf(P.Wh0, ax, -lbx)));
        float g1y = relu_(fmaf(P.Wi1, xy, fmaf(P.Wh1, ay, -lby)));
        float g2x = relu_(fmaf(P.W10, g1x, ubx - lbx));
        float g2y = relu_(fmaf(P.W11, g1y, uby - lby));
        hx = fmaf(P.W20, g2x, ubx);
        hy = fmaf(P.W21, g2y, uby);

        __stcs(o0 + offt, hx);
        __stcs(o1 + offt, hy);
    }
    if (write_hT) {
        out[2 * TB + b] = hx;
        out[2 * TB + B + b] = hy;
    }
}

extern "C" void kernel_launch(void* const* d_in, const int* in_sizes, int n_in,
                              void* d_out, int out_size)
{
    // 0 input (D,T,B), 1 target, 2 returns (D,T,B), 3 hidden (D,1,B),
    // 4 w_input, 5 w_hidden, 6 b_hidden, 7 w_fc1, 8 w_fc2, 9 w_rotate
    const float* x   = (const float*)d_in[0];
    const float* tgt = (const float*)d_in[1];
    const float* ret = (const float*)d_in[2];
    const float* wi  = (const float*)d_in[4];
    const float* wh  = (const float*)d_in[5];
    const float* bh  = (const float*)d_in[6];
    const float* w1  = (const float*)d_in[7];
    const float* w2  = (const float*)d_in[8];
    const float* wr  = (const float*)d_in[9];
    float* out = (float*)d_out;

    const int D = 2;
    const int B = in_sizes[3] / D;
    const int T = in_sizes[0] / (D * B);
    const int write_hT = (out_size >= D * T * B + D * B) ? 1 : 0;

    constexpr int TS = 512, BS = 16384, PF = 8;
    if (T == TS && B == BS) {
        // one warp per CTA, 256 CTAs -> work on all 148 SMs
        const int threads = 32;
        const int blocks = (BS / 2) / threads;   // 256
        ntr_rnn_f32x2<TS, BS, PF><<<blocks, threads>>>(
            x, ret, tgt, wi, wh, bh, w1, w2, wr, out, write_hT);
    } else {
        const int threads = 128;
        const int blocks = (B + threads - 1) / threads;
        ntr_rnn_generic<<<blocks, threads>>>(
            x, ret, tgt, wi, wh, bh, w1, w2, wr, out, T, B, write_hT);
    }
}

// round 6
// speedup vs baseline: 1.8857x; 1.8857x over previous
#include <cuda_runtime.h>

// NoTradeRegionRNN: D=2 channel RNN scan, T timesteps, B independent lanes.
// x, returns: (D, T, B) row-major. output: (D, T, B) then hT (D, 1, B).
//
// R6: cp.async (LDGSTS) staged SMEM ring with precise wait_group distance.
// Register software-pipelining (R3-R5) could not hide DRAM latency: ptxas
// aliases many LDGs onto the 6 scoreboard slots, so reading a prefetch
// buffer waits (max-of-arms) on loads issued only 1-2 steps earlier,
// re-exposing ~600 cycles of latency per step. cp.async.wait_group tracks
// completion per commit-group: waiting for "all but the newest S-2 groups"
// exactly expresses a prefetch distance of S-1 steps with zero aliasing.
// Stage s+1 is LDS-prefetched into registers during step s, keeping the
// 29-cycle LDS latency off the serial chain.

__device__ __forceinline__ float relu_(float v) { return fmaxf(v, 0.0f); }
__device__ __forceinline__ float clamp_(float v, float lo, float hi) {
    return fminf(fmaxf(v, lo), hi);
}
__device__ __forceinline__ float frcp_(float v) {
    float r; asm("rcp.approx.f32 %0, %1;" : "=f"(r) : "f"(v)); return r;
}
__device__ __forceinline__ void cp4_(unsigned dst, const void* src) {
    asm volatile("cp.async.ca.shared.global [%0], [%1], 4;" :: "r"(dst), "l"(src));
}
__device__ __forceinline__ void cp_commit_() {
    asm volatile("cp.async.commit_group;");
}
template <int N>
__device__ __forceinline__ void cp_wait_() {
    asm volatile("cp.async.wait_group %0;" :: "n"(N));
}

// ---------------- parameter derivation ----------------
struct Params {
    float ac, bd;
    float Wi0, Wi1, Wh0, Wh1, W10, W11, W20, W21;
    float C_lbx, LO_lbx, HI_lbx;   // val = clamp(fma(a, slope, C), LO, HI)
    float C_ubx, LO_ubx, HI_ubx;
    float C_lby, LO_lby, HI_lby;
    float C_uby, LO_uby, HI_uby;
};

__device__ __forceinline__ Params make_params(
    const float* __restrict__ tgt, const float* __restrict__ wi,
    const float* __restrict__ wh,  const float* __restrict__ bh,
    const float* __restrict__ w1,  const float* __restrict__ w2,
    const float* __restrict__ wr)
{
    Params P;
    const float wr00 = wr[0], wr01 = wr[1], wr10 = wr[2], wr11 = wr[3];
    const float bh0 = bh[0], bh1 = bh[1];
    const float t0 = tgt[0], t1 = tgt[1];
    P.Wi0 = wi[0]; P.Wi1 = wi[1];
    P.Wh0 = wh[0]; P.Wh1 = wh[1];
    P.W10 = w1[0]; P.W11 = w1[1];
    P.W20 = w2[0]; P.W21 = w2[1];
    P.ac = wr10 / wr00;
    P.bd = wr01 / wr11;

    // Corners: k0:(-,-) k1:(-,+) k2:(+,+) k3:(+,-) applied to (bh0, bh1)
    float Cx[4], Cy[4];
    const float s0[4] = {-1.f, -1.f, 1.f, 1.f};
    const float s1[4] = {-1.f,  1.f, 1.f, -1.f};
#pragma unroll
    for (int k = 0; k < 4; ++k) {
        float vx = s0[k] * bh0, vy = s1[k] * bh1;
        Cx[k] = wr00 * vx + wr01 * vy + t0;
        Cy[k] = wr10 * vx + wr11 * vy + t1;
    }
    const bool bdp = (P.bd >= 0.0f);
    const bool acp = (P.ac >= 0.0f);
    // bound: w=(a-c)*slope; val = o - relu(A - relu(w)) == clamp(w+o-A, o-A, o)
    {
        float c = bdp ? Cy[0] : Cy[1], A = fabsf(Cx[1] - Cx[0]), o = bdp ? Cx[1] : Cx[0];
        P.C_lbx = -c * P.bd + o - A; P.LO_lbx = o - A; P.HI_lbx = o;
    }
    {
        float c = bdp ? Cy[3] : Cy[2], A = fabsf(Cx[2] - Cx[3]), o = bdp ? Cx[2] : Cx[3];
        P.C_ubx = -c * P.bd + o - A; P.LO_ubx = o - A; P.HI_ubx = o;
    }
    {
        float c = acp ? Cx[0] : Cx[3], A = fabsf(Cy[0] - Cy[3]), o = acp ? Cy[3] : Cy[0];
        P.C_lby = -c * P.ac + o - A; P.LO_lby = o - A; P.HI_lby = o;
    }
    {
        float c = acp ? Cx[1] : Cx[2], A = fabsf(Cy[1] - Cy[2]), o = acp ? Cy[2] : Cy[1];
        P.C_uby = -c * P.ac + o - A; P.LO_uby = o - A; P.HI_uby = o;
    }
    return P;
}

__device__ __forceinline__ void ntr_step(const Params& P,
                                         float& hx, float& hy,
                                         float rx, float ry,
                                         float xx, float xy)
{
    float denom = fmaf(hx, rx, fmaf(hy, ry, 1.0f));
    float inv = frcp_(denom);
    float ax = fmaf(hx, rx, hx) * inv;      // hx*(1+rx)/denom
    float ay = fmaf(hy, ry, hy) * inv;

    float lbx = clamp_(fmaf(ay, P.bd, P.C_lbx), P.LO_lbx, P.HI_lbx);
    float ubx = clamp_(fmaf(ay, P.bd, P.C_ubx), P.LO_ubx, P.HI_ubx);
    float lby = clamp_(fmaf(ax, P.ac, P.C_lby), P.LO_lby, P.HI_lby);
    float uby = clamp_(fmaf(ax, P.ac, P.C_uby), P.LO_uby, P.HI_uby);

    float g1x = relu_(fmaf(P.Wi0, xx, fmaf(P.Wh0, ax, -lbx)));
    float g1y = relu_(fmaf(P.Wi1, xy, fmaf(P.Wh1, ay, -lby)));
    float g2x = relu_(fmaf(P.W10, g1x, ubx - lbx));
    float g2y = relu_(fmaf(P.W11, g1y, uby - lby));
    hx = fmaf(P.W20, g2x, ubx);
    hy = fmaf(P.W21, g2y, uby);
}

// ---------------- cp.async staged kernel (T=512, B=16384) ----------------
// Stage layout: stage j occupies floats [(j*4+p)*128 + tid], p = plane
// (0: r0, 1: r1, 2: x0, 3: x1). 16 stages * 2KB = 32KB static SMEM.
template <int T, int B>
__global__ void __launch_bounds__(128)
ntr_rnn_cpasync(const float* __restrict__ x,
                const float* __restrict__ ret,
                const float* __restrict__ tgt,
                const float* __restrict__ wi,
                const float* __restrict__ wh,
                const float* __restrict__ bh,
                const float* __restrict__ w1,
                const float* __restrict__ w2,
                const float* __restrict__ wr,
                float* __restrict__ out,
                int write_hT)
{
    constexpr int S = 16;                    // ring stages
    constexpr int STEPS = T - 1;             // 511
    constexpr int MAIN_GROUPS = (STEPS - (S - 1)) / S;   // 31
    constexpr int TAIL = STEPS - MAIN_GROUPS * S;        // 15
    static_assert(MAIN_GROUPS * S + TAIL == STEPS, "");

    __shared__ __align__(16) float smem[S * 4 * 128];

    const int tid = threadIdx.x;
    const int b = blockIdx.x * blockDim.x + tid;
    const Params P = make_params(tgt, wi, wh, bh, w1, w2, wr);

    const size_t TB = (size_t)T * (size_t)B;

    // global stream bases for this lane; step s reads r at t=s, x at t=s+1,
    // writes out at t=s+1.
    const float* pr0 = ret + b;
    const float* pr1 = ret + TB + b;
    const float* px0 = x + B + b;
    const float* px1 = x + TB + B + b;
    float* po0 = out + B + b;
    float* po1 = out + TB + B + b;

    unsigned smem_u32 = (unsigned)__cvta_generic_to_shared(smem) + tid * 4u;
    // address of (stage j, plane p) for this thread:
    //   smem_u32 + (j*4+p)*512
#define STAGE_ADDR(j, p) (smem_u32 + ((j) * 4 + (p)) * 512u)
#define STAGE_VAL(j, p)  (smem[((j) * 4 + (p)) * 128 + tid])

    // h0 = x[:, 0, :]
    float hx = __ldg(x + b);
    float hy = __ldg(x + TB + b);
    out[b] = hx;
    out[TB + b] = hy;

    // ---- prologue: issue stages for steps 0..S-2 ----
#pragma unroll
    for (int j = 0; j < S - 1; ++j) {
        cp4_(STAGE_ADDR(j, 0), pr0 + (size_t)j * B);
        cp4_(STAGE_ADDR(j, 1), pr1 + (size_t)j * B);
        cp4_(STAGE_ADDR(j, 2), px0 + (size_t)j * B);
        cp4_(STAGE_ADDR(j, 3), px1 + (size_t)j * B);
        cp_commit_();
    }
    cp_wait_<S - 2>();           // step 0 data has landed
    float rx = STAGE_VAL(0, 0);
    float ry = STAGE_VAL(0, 1);
    float xx = STAGE_VAL(0, 2);
    float xy = STAGE_VAL(0, 3);

    // ---- main loop: MAIN_GROUPS groups of S steps, everything immediate ----
    for (int g = 0; g < MAIN_GROUPS; ++g) {
#pragma unroll
        for (int j = 0; j < S; ++j) {
            // issue step s+S-1 into stage (j+S-1)&(S-1) == (j-1)&(S-1)
            constexpr_hint:;
            const int stg_i = (j + S - 1) & (S - 1);
            cp4_(STAGE_ADDR(stg_i, 0), pr0 + (size_t)(j + S - 1) * B);
            cp4_(STAGE_ADDR(stg_i, 1), pr1 + (size_t)(j + S - 1) * B);
            cp4_(STAGE_ADDR(stg_i, 2), px0 + (size_t)(j + S - 1) * B);
            cp4_(STAGE_ADDR(stg_i, 3), px1 + (size_t)(j + S - 1) * B);
            cp_commit_();
            cp_wait_<S - 2>();   // step s+1 data has landed
            // register-prefetch step s+1 from stage (j+1)&(S-1)
            const int stg_n = (j + 1) & (S - 1);
            float nrx = STAGE_VAL(stg_n, 0);
            float nry = STAGE_VAL(stg_n, 1);
            float nxx = STAGE_VAL(stg_n, 2);
            float nxy = STAGE_VAL(stg_n, 3);
            // compute step s from current registers
            ntr_step(P, hx, hy, rx, ry, xx, xy);
            __stcs(po0 + (size_t)j * B, hx);
            __stcs(po1 + (size_t)j * B, hy);
            rx = nrx; ry = nry; xx = nxx; xy = nxy;
        }
        pr0 += (size_t)S * B; pr1 += (size_t)S * B;
        px0 += (size_t)S * B; px1 += (size_t)S * B;
        po0 += (size_t)S * B; po1 += (size_t)S * B;
    }

    // ---- tail: TAIL steps, all data already issued; drain once ----
    cp_wait_<0>();
#pragma unroll
    for (int j = 0; j < TAIL; ++j) {
        float nrx = 0.f, nry = 0.f, nxx = 0.f, nxy = 0.f;
        if (j < TAIL - 1) {
            const int stg_n = (j + 1) & (S - 1);
            nrx = STAGE_VAL(stg_n, 0);
            nry = STAGE_VAL(stg_n, 1);
            nxx = STAGE_VAL(stg_n, 2);
            nxy = STAGE_VAL(stg_n, 3);
        }
        ntr_step(P, hx, hy, rx, ry, xx, xy);
        __stcs(po0 + (size_t)j * B, hx);
        __stcs(po1 + (size_t)j * B, hy);
        rx = nrx; ry = nry; xx = nxx; xy = nxy;
    }
#undef STAGE_ADDR
#undef STAGE_VAL

    if (write_hT) {
        out[2 * TB + b] = hx;
        out[2 * TB + B + b] = hy;
    }
}

// ---------------- generic fallback (any T, B) ----------------
__global__ void __launch_bounds__(128)
ntr_rnn_generic(const float* __restrict__ x,
                const float* __restrict__ ret,
                const float* __restrict__ tgt,
                const float* __restrict__ wi,
                const float* __restrict__ wh,
                const float* __restrict__ bh,
                const float* __restrict__ w1,
                const float* __restrict__ w2,
                const float* __restrict__ wr,
                float* __restrict__ out,
                int T, int B, int write_hT)
{
    const int b = blockIdx.x * blockDim.x + threadIdx.x;
    if (b >= B) return;
    const Params P = make_params(tgt, wi, wh, bh, w1, w2, wr);

    const size_t TB = (size_t)T * (size_t)B;
    const float* r0 = ret + b;
    const float* r1 = ret + TB + b;
    const float* x0 = x + b;
    const float* x1 = x + TB + b;
    float* o0 = out + b;
    float* o1 = out + TB + b;

    float hx = __ldg(x0);
    float hy = __ldg(x1);
    o0[0] = hx; o1[0] = hy;

    for (int t = 1; t < T; ++t) {
        size_t offp = (size_t)(t - 1) * B;
        size_t offt = (size_t)t * B;
        float rx = __ldcs(r0 + offp), ry = __ldcs(r1 + offp);
        float xx = __ldcs(x0 + offt), xy = __ldcs(x1 + offt);
        ntr_step(P, hx, hy, rx, ry, xx, xy);
        __stcs(o0 + offt, hx);
        __stcs(o1 + offt, hy);
    }
    if (write_hT) {
        out[2 * TB + b] = hx;
        out[2 * TB + B + b] = hy;
    }
}

extern "C" void kernel_launch(void* const* d_in, const int* in_sizes, int n_in,
                              void* d_out, int out_size)
{
    // 0 input (D,T,B), 1 target, 2 returns (D,T,B), 3 hidden (D,1,B),
    // 4 w_input, 5 w_hidden, 6 b_hidden, 7 w_fc1, 8 w_fc2, 9 w_rotate
    const float* x   = (const float*)d_in[0];
    const float* tgt = (const float*)d_in[1];
    const float* ret = (const float*)d_in[2];
    const float* wi  = (const float*)d_in[4];
    const float* wh  = (const float*)d_in[5];
    const float* bh  = (const float*)d_in[6];
    const float* w1  = (const float*)d_in[7];
    const float* w2  = (const float*)d_in[8];
    const float* wr  = (const float*)d_in[9];
    float* out = (float*)d_out;

    const int D = 2;
    const int B = in_sizes[3] / D;
    const int T = in_sizes[0] / (D * B);
    const int write_hT = (out_size >= D * T * B + D * B) ? 1 : 0;

    constexpr int TS = 512, BS = 16384;
    if (T == TS && B == BS) {
        const int threads = 128;
        const int blocks = BS / threads;     // 128 CTAs
        ntr_rnn_cpasync<TS, BS><<<blocks, threads>>>(
            x, ret, tgt, wi, wh, bh, w1, w2, wr, out, write_hT);
    } else {
        const int threads = 128;
        const int blocks = (B + threads - 1) / threads;
        ntr_rnn_generic<<<blocks, threads>>>(
            x, ret, tgt, wi, wh, bh, w1, w2, wr, out, T, B, write_hT);
    }
}

// round 7
// speedup vs baseline: 2.0279x; 1.0754x over previous
#include <cuda_runtime.h>

// NoTradeRegionRNN: D=2 channel RNN scan, T timesteps, B independent lanes.
// x, returns: (D, T, B) row-major. output: (D, T, B) then hT (D, 1, B).
//
// R7: cp.async SMEM ring (R6) with ONE 16-byte cp.async.cg per thread per
// step instead of four 4-byte ones (4x fewer LDGSTS issue slots, less MIO
// pressure). Each warp's cp.asyncs cover exactly the 4 planes x 32 lanes its
// own threads consume (wait_group is per-warp - no cross-warp races).
// Stage layout [warp][plane][lane]: conflict-free for both the 16B async
// writes and the 4 scalar LDS reads. Next step's operands are LDS-prefetched
// into registers one step ahead, keeping LDS latency off the serial chain.

__device__ __forceinline__ float relu_(float v) { return fmaxf(v, 0.0f); }
__device__ __forceinline__ float clamp_(float v, float lo, float hi) {
    return fminf(fmaxf(v, lo), hi);
}
__device__ __forceinline__ float frcp_(float v) {
    float r; asm("rcp.approx.f32 %0, %1;" : "=f"(r) : "f"(v)); return r;
}
__device__ __forceinline__ void cp16_(unsigned dst, const void* src) {
    asm volatile("cp.async.cg.shared.global [%0], [%1], 16;" :: "r"(dst), "l"(src));
}
__device__ __forceinline__ void cp4_(unsigned dst, const void* src) {
    asm volatile("cp.async.ca.shared.global [%0], [%1], 4;" :: "r"(dst), "l"(src));
}
__device__ __forceinline__ void cp_commit_() {
    asm volatile("cp.async.commit_group;");
}
template <int N>
__device__ __forceinline__ void cp_wait_() {
    asm volatile("cp.async.wait_group %0;" :: "n"(N));
}

// ---------------- parameter derivation ----------------
struct Params {
    float ac, bd;
    float Wi0, Wi1, Wh0, Wh1, W10, W11, W20, W21;
    float C_lbx, LO_lbx, HI_lbx;   // val = clamp(fma(a, slope, C), LO, HI)
    float C_ubx, LO_ubx, HI_ubx;
    float C_lby, LO_lby, HI_lby;
    float C_uby, LO_uby, HI_uby;
};

__device__ __forceinline__ Params make_params(
    const float* __restrict__ tgt, const float* __restrict__ wi,
    const float* __restrict__ wh,  const float* __restrict__ bh,
    const float* __restrict__ w1,  const float* __restrict__ w2,
    const float* __restrict__ wr)
{
    Params P;
    const float wr00 = wr[0], wr01 = wr[1], wr10 = wr[2], wr11 = wr[3];
    const float bh0 = bh[0], bh1 = bh[1];
    const float t0 = tgt[0], t1 = tgt[1];
    P.Wi0 = wi[0]; P.Wi1 = wi[1];
    P.Wh0 = wh[0]; P.Wh1 = wh[1];
    P.W10 = w1[0]; P.W11 = w1[1];
    P.W20 = w2[0]; P.W21 = w2[1];
    P.ac = wr10 / wr00;
    P.bd = wr01 / wr11;

    // Corners: k0:(-,-) k1:(-,+) k2:(+,+) k3:(+,-) applied to (bh0, bh1)
    float Cx[4], Cy[4];
    const float s0[4] = {-1.f, -1.f, 1.f, 1.f};
    const float s1[4] = {-1.f,  1.f, 1.f, -1.f};
#pragma unroll
    for (int k = 0; k < 4; ++k) {
        float vx = s0[k] * bh0, vy = s1[k] * bh1;
        Cx[k] = wr00 * vx + wr01 * vy + t0;
        Cy[k] = wr10 * vx + wr11 * vy + t1;
    }
    const bool bdp = (P.bd >= 0.0f);
    const bool acp = (P.ac >= 0.0f);
    // bound: w=(a-c)*slope; val = o - relu(A - relu(w)) == clamp(w+o-A, o-A, o)
    {
        float c = bdp ? Cy[0] : Cy[1], A = fabsf(Cx[1] - Cx[0]), o = bdp ? Cx[1] : Cx[0];
        P.C_lbx = -c * P.bd + o - A; P.LO_lbx = o - A; P.HI_lbx = o;
    }
    {
        float c = bdp ? Cy[3] : Cy[2], A = fabsf(Cx[2] - Cx[3]), o = bdp ? Cx[2] : Cx[3];
        P.C_ubx = -c * P.bd + o - A; P.LO_ubx = o - A; P.HI_ubx = o;
    }
    {
        float c = acp ? Cx[0] : Cx[3], A = fabsf(Cy[0] - Cy[3]), o = acp ? Cy[3] : Cy[0];
        P.C_lby = -c * P.ac + o - A; P.LO_lby = o - A; P.HI_lby = o;
    }
    {
        float c = acp ? Cx[1] : Cx[2], A = fabsf(Cy[1] - Cy[2]), o = acp ? Cy[2] : Cy[1];
        P.C_uby = -c * P.ac + o - A; P.LO_uby = o - A; P.HI_uby = o;
    }
    return P;
}

__device__ __forceinline__ void ntr_step(const Params& P,
                                         float& hx, float& hy,
                                         float rx, float ry,
                                         float xx, float xy)
{
    float denom = fmaf(hx, rx, fmaf(hy, ry, 1.0f));
    float inv = frcp_(denom);
    float ax = fmaf(hx, rx, hx) * inv;      // hx*(1+rx)/denom
    float ay = fmaf(hy, ry, hy) * inv;

    float lbx = clamp_(fmaf(ay, P.bd, P.C_lbx), P.LO_lbx, P.HI_lbx);
    float ubx = clamp_(fmaf(ay, P.bd, P.C_ubx), P.LO_ubx, P.HI_ubx);
    float lby = clamp_(fmaf(ax, P.ac, P.C_lby), P.LO_lby, P.HI_lby);
    float uby = clamp_(fmaf(ax, P.ac, P.C_uby), P.LO_uby, P.HI_uby);

    float g1x = relu_(fmaf(P.Wi0, xx, fmaf(P.Wh0, ax, -lbx)));
    float g1y = relu_(fmaf(P.Wi1, xy, fmaf(P.Wh1, ay, -lby)));
    float g2x = relu_(fmaf(P.W10, g1x, ubx - lbx));
    float g2y = relu_(fmaf(P.W11, g1y, uby - lby));
    hx = fmaf(P.W20, g2x, ubx);
    hy = fmaf(P.W21, g2y, uby);
}

// ---------------- cp.async staged kernel (T=512, B=16384) ----------------
// Stage j (2048 B): warp w region [w*512, w*512+512) holds plane p at
// [p*128, p*128+128) = 32 lanes' floats. Per step each thread issues ONE
// 16B cp.async for (plane = lane>>3, chunk = lane&7) of its own warp.
template <int T, int B>
__global__ void __launch_bounds__(128)
ntr_rnn_cpasync(const float* __restrict__ x,
                const float* __restrict__ ret,
                const float* __restrict__ tgt,
                const float* __restrict__ wi,
                const float* __restrict__ wh,
                const float* __restrict__ bh,
                const float* __restrict__ w1,
                const float* __restrict__ w2,
                const float* __restrict__ wr,
                float* __restrict__ out,
                int write_hT)
{
    constexpr int S = 16;                    // ring stages
    constexpr int STEPS = T - 1;             // 511
    constexpr int MAIN_GROUPS = (STEPS - (S - 1)) / S;   // 31
    constexpr int TAIL = STEPS - MAIN_GROUPS * S;        // 15
    static_assert(MAIN_GROUPS * S + TAIL == STEPS, "");

    __shared__ __align__(16) float smem[S * 4 * 128];

    const int tid = threadIdx.x;
    const int b = blockIdx.x * blockDim.x + tid;
    const Params P = make_params(tgt, wi, wh, bh, w1, w2, wr);

    const size_t TB = (size_t)T * (size_t)B;

    // ---- cp.async source/dest for THIS thread ----
    const int w = tid >> 5;          // warp in CTA
    const int m = tid & 31;          // lane
    const int p = m >> 3;            // plane this lane copies
    const int sub = m & 7;           // 16B chunk within the warp's 128B plane
    // plane bases: 0 -> r0 (t=0), 1 -> r1, 2 -> x0 (t=1), 3 -> x1
    const float* plane_base =
        (p == 0) ? ret :
        (p == 1) ? ret + TB :
        (p == 2) ? x + B :
                   x + TB + B;
    // byte source for step 0 of this thread's chunk
    const float* cp_src = plane_base + (size_t)blockIdx.x * 128 + w * 32 + sub * 4;

    const unsigned smem_base = (unsigned)__cvta_generic_to_shared(smem);
    const unsigned cp_dst0 = smem_base + (unsigned)(w * 512 + p * 128 + sub * 16);
#define STAGE_DST(stg)   (cp_dst0 + (unsigned)(stg) * 2048u)
    // compute-side value: plane pp of this thread's lane at stage stg
#define STAGE_VAL(stg, pp) (smem[(stg) * 512 + w * 128 + (pp) * 32 + m])

    // output pointers; step s writes t = s+1
    float* po0 = out + B + b;
    float* po1 = out + TB + B + b;

    // h0 = x[:, 0, :]
    float hx = __ldg(x + b);
    float hy = __ldg(x + TB + b);
    out[b] = hx;
    out[TB + b] = hy;

    // ---- prologue: issue stages for steps 0..S-2 ----
#pragma unroll
    for (int j = 0; j < S - 1; ++j) {
        cp16_(STAGE_DST(j), cp_src + (size_t)j * B);
        cp_commit_();
    }
    cp_wait_<S - 2>();           // step 0 data has landed
    float rx = STAGE_VAL(0, 0);
    float ry = STAGE_VAL(0, 1);
    float xx = STAGE_VAL(0, 2);
    float xy = STAGE_VAL(0, 3);

    // ---- main loop: MAIN_GROUPS groups of S steps ----
    for (int g = 0; g < MAIN_GROUPS; ++g) {
#pragma unroll
        for (int j = 0; j < S; ++j) {
            // issue step g*S + j + S-1 into stage (j-1)&(S-1)
            const int stg_i = (j + S - 1) & (S - 1);
            cp16_(STAGE_DST(stg_i), cp_src + (size_t)(j + S - 1) * B);
            cp_commit_();
            cp_wait_<S - 2>();   // step s+1 data has landed
            // register-prefetch step s+1 from stage (j+1)&(S-1)
            const int stg_n = (j + 1) & (S - 1);
            float nrx = STAGE_VAL(stg_n, 0);
            float nry = STAGE_VAL(stg_n, 1);
            float nxx = STAGE_VAL(stg_n, 2);
            float nxy = STAGE_VAL(stg_n, 3);
            // compute step s from current registers
            ntr_step(P, hx, hy, rx, ry, xx, xy);
            __stcs(po0 + (size_t)j * B, hx);
            __stcs(po1 + (size_t)j * B, hy);
            rx = nrx; ry = nry; xx = nxx; xy = nxy;
        }
        cp_src += (size_t)S * B;
        po0 += (size_t)S * B; po1 += (size_t)S * B;
    }

    // ---- tail: TAIL steps, all data already issued; drain once ----
    cp_wait_<0>();
#pragma unroll
    for (int j = 0; j < TAIL; ++j) {
        float nrx = 0.f, nry = 0.f, nxx = 0.f, nxy = 0.f;
        if (j < TAIL - 1) {
            const int stg_n = (j + 1) & (S - 1);
            nrx = STAGE_VAL(stg_n, 0);
            nry = STAGE_VAL(stg_n, 1);
            nxx = STAGE_VAL(stg_n, 2);
            nxy = STAGE_VAL(stg_n, 3);
        }
        ntr_step(P, hx, hy, rx, ry, xx, xy);
        __stcs(po0 + (size_t)j * B, hx);
        __stcs(po1 + (size_t)j * B, hy);
        rx = nrx; ry = nry; xx = nxx; xy = nxy;
    }
#undef STAGE_DST
#undef STAGE_VAL

    if (write_hT) {
        out[2 * TB + b] = hx;
        out[2 * TB + B + b] = hy;
    }
}

// ---------------- generic fallback (any T, B) ----------------
__global__ void __launch_bounds__(128)
ntr_rnn_generic(const float* __restrict__ x,
                const float* __restrict__ ret,
                const float* __restrict__ tgt,
                const float* __restrict__ wi,
                const float* __restrict__ wh,
                const float* __restrict__ bh,
                const float* __restrict__ w1,
                const float* __restrict__ w2,
                const float* __restrict__ wr,
                float* __restrict__ out,
                int T, int B, int write_hT)
{
    const int b = blockIdx.x * blockDim.x + threadIdx.x;
    if (b >= B) return;
    const Params P = make_params(tgt, wi, wh, bh, w1, w2, wr);

    const size_t TB = (size_t)T * (size_t)B;
    const float* r0 = ret + b;
    const float* r1 = ret + TB + b;
    const float* x0 = x + b;
    const float* x1 = x + TB + b;
    float* o0 = out + b;
    float* o1 = out + TB + b;

    float hx = __ldg(x0);
    float hy = __ldg(x1);
    o0[0] = hx; o1[0] = hy;

    for (int t = 1; t < T; ++t) {
        size_t offp = (size_t)(t - 1) * B;
        size_t offt = (size_t)t * B;
        float rx = __ldcs(r0 + offp), ry = __ldcs(r1 + offp);
        float xx = __ldcs(x0 + offt), xy = __ldcs(x1 + offt);
        ntr_step(P, hx, hy, rx, ry, xx, xy);
        __stcs(o0 + offt, hx);
        __stcs(o1 + offt, hy);
    }
    if (write_hT) {
        out[2 * TB + b] = hx;
        out[2 * TB + B + b] = hy;
    }
}

extern "C" void kernel_launch(void* const* d_in, const int* in_sizes, int n_in,
                              void* d_out, int out_size)
{
    // 0 input (D,T,B), 1 target, 2 returns (D,T,B), 3 hidden (D,1,B),
    // 4 w_input, 5 w_hidden, 6 b_hidden, 7 w_fc1, 8 w_fc2, 9 w_rotate
    const float* x   = (const float*)d_in[0];
    const float* tgt = (const float*)d_in[1];
    const float* ret = (const float*)d_in[2];
    const float* wi  = (const float*)d_in[4];
    const float* wh  = (const float*)d_in[5];
    const float* bh  = (const float*)d_in[6];
    const float* w1  = (const float*)d_in[7];
    const float* w2  = (const float*)d_in[8];
    const float* wr  = (const float*)d_in[9];
    float* out = (float*)d_out;

    const int D = 2;
    const int B = in_sizes[3] / D;
    const int T = in_sizes[0] / (D * B);
    const int write_hT = (out_size >= D * T * B + D * B) ? 1 : 0;

    constexpr int TS = 512, BS = 16384;
    if (T == TS && B == BS) {
        const int threads = 128;
        const int blocks = BS / threads;     // 128 CTAs
        ntr_rnn_cpasync<TS, BS><<<blocks, threads>>>(
            x, ret, tgt, wi, wh, bh, w1, w2, wr, out, write_hT);
    } else {
        const int threads = 128;
        const int blocks = (B + threads - 1) / threads;
        ntr_rnn_generic<<<blocks, threads>>>(
            x, ret, tgt, wi, wh, bh, w1, w2, wr, out, T, B, write_hT);
    }
}